// round 1
// baseline (speedup 1.0000x reference)
#include <cuda_runtime.h>

// Problem constants
#define NTOK 4096      // N = D*H*W
#define CB   32        // cbar
#define CIN  64        // C
#define BATCH 2
#define BM   64        // query tile
#define BN   64        // key tile
#define NT   256       // threads per block (attn)

// Scratch (no cudaMalloc allowed)
__device__ float g_f  [BATCH * NTOK * CB];
__device__ float g_g  [BATCH * NTOK * CB];
__device__ float g_hv [BATCH * NTOK * CB];
__device__ float g_bhv[BATCH * NTOK * CB];

// ---------------------------------------------------------------------------
// Kernel 1: per-voxel projections f = xW_f+b_f, g = xW_g+b_g, hv = xW_h+b_h
// One thread per (row, cbar-col); a warp covers exactly one row (32 cols):
// x loads broadcast, W loads coalesced (W is 8KB, L1-resident).
// ---------------------------------------------------------------------------
__global__ __launch_bounds__(256) void proj_kernel(
    const float* __restrict__ x,
    const float* __restrict__ Wf, const float* __restrict__ bf,
    const float* __restrict__ Wg, const float* __restrict__ bg,
    const float* __restrict__ Wh, const float* __restrict__ bh)
{
    int idx = blockIdx.x * blockDim.x + threadIdx.x;   // [0, B*N*CB)
    int row = idx >> 5;
    int c   = idx & 31;
    const float* xr = x + row * CIN;
    float af = bf[c], ag = bg[c], ah = bh[c];
#pragma unroll 8
    for (int k = 0; k < CIN; k++) {
        float xv = xr[k];
        af = fmaf(xv, Wf[k * CB + c], af);
        ag = fmaf(xv, Wg[k * CB + c], ag);
        ah = fmaf(xv, Wh[k * CB + c], ah);
    }
    g_f[idx] = af;
    g_g[idx] = ag;
    g_hv[idx] = ah;
}

// ---------------------------------------------------------------------------
// Kernel 2: flash attention over N=4096 keys, head dim cbar=32.
// Block = (BM=64 queries) x (full key sweep in BN=64 tiles), 256 threads.
// Thread (ty,tx): ty = t/16 owns query rows ty*4..+3; tx = t%16 owns
//   GEMM1: key cols tx*4..+3 ; GEMM2: cbar cols tx*2..+1.
// G and F tiles stored k-major (transposed) in SMEM -> float4 fragment loads
// are contiguous & conflict-free. P staged in SMEM (stride BN+4).
// ---------------------------------------------------------------------------
__global__ __launch_bounds__(NT) void attn_kernel()
{
    __shared__ float sGt[CB][BM];        // g transposed: [k][query]
    __shared__ float sFt[CB][BN];        // f transposed: [k][key]
    __shared__ float sHV[BN][CB];        // hv row-major: [key][cbar]
    __shared__ float sP [BM][BN + 4];    // probabilities tile

    const int b  = blockIdx.y;
    const int q0 = blockIdx.x * BM;
    const int t  = threadIdx.x;
    const int tx = t & 15;
    const int ty = t >> 4;

    // ---- Load G tile once, transposed into sGt -------------------------
    {
        const float* gb = g_g + (size_t)(b * NTOK + q0) * CB;
        int row = t >> 2;        // 0..63 query within tile
        int qd  = t & 3;         // covers k quads qd and qd+4
        float4 v1 = *(const float4*)(gb + row * CB + qd * 4);
        float4 v2 = *(const float4*)(gb + row * CB + (qd + 4) * 4);
        sGt[qd * 4 + 0][row] = v1.x;  sGt[qd * 4 + 1][row] = v1.y;
        sGt[qd * 4 + 2][row] = v1.z;  sGt[qd * 4 + 3][row] = v1.w;
        sGt[qd * 4 + 16][row] = v2.x; sGt[qd * 4 + 17][row] = v2.y;
        sGt[qd * 4 + 18][row] = v2.z; sGt[qd * 4 + 19][row] = v2.w;
    }

    float m[4], l[4];
    float acc[4][2];
#pragma unroll
    for (int i = 0; i < 4; i++) {
        m[i] = -1e30f; l[i] = 0.f;
        acc[i][0] = 0.f; acc[i][1] = 0.f;
    }

    const int c0 = tx * 2;   // cbar cols owned in GEMM2

    for (int kt = 0; kt < NTOK / BN; kt++) {
        const float* fb = g_f  + (size_t)(b * NTOK + kt * BN) * CB;
        const float* hb = g_hv + (size_t)(b * NTOK + kt * BN) * CB;

        __syncthreads();   // previous iteration done reading sFt/sHV (+ first-iter sGt)

        // ---- Stage F (transposed) and HV tiles -------------------------
        {
            int row = t >> 2;
            int qd  = t & 3;
            float4 v1 = *(const float4*)(fb + row * CB + qd * 4);
            float4 v2 = *(const float4*)(fb + row * CB + (qd + 4) * 4);
            sFt[qd * 4 + 0][row] = v1.x;  sFt[qd * 4 + 1][row] = v1.y;
            sFt[qd * 4 + 2][row] = v1.z;  sFt[qd * 4 + 3][row] = v1.w;
            sFt[qd * 4 + 16][row] = v2.x; sFt[qd * 4 + 17][row] = v2.y;
            sFt[qd * 4 + 18][row] = v2.z; sFt[qd * 4 + 19][row] = v2.w;

            float4*       sh  = (float4*)&sHV[0][0];
            const float4* hb4 = (const float4*)hb;
            sh[t]      = hb4[t];
            sh[t + NT] = hb4[t + NT];
        }
        __syncthreads();

        // ---- GEMM1: S[4][4] = G(rows ty*4..) . F(keys tx*4..) ----------
        float s00 = 0.f, s01 = 0.f, s02 = 0.f, s03 = 0.f;
        float s10 = 0.f, s11 = 0.f, s12 = 0.f, s13 = 0.f;
        float s20 = 0.f, s21 = 0.f, s22 = 0.f, s23 = 0.f;
        float s30 = 0.f, s31 = 0.f, s32 = 0.f, s33 = 0.f;
#pragma unroll 8
        for (int k = 0; k < CB; k++) {
            float4 gv = *(const float4*)&sGt[k][ty * 4];
            float4 fv = *(const float4*)&sFt[k][tx * 4];
            s00 = fmaf(gv.x, fv.x, s00); s01 = fmaf(gv.x, fv.y, s01);
            s02 = fmaf(gv.x, fv.z, s02); s03 = fmaf(gv.x, fv.w, s03);
            s10 = fmaf(gv.y, fv.x, s10); s11 = fmaf(gv.y, fv.y, s11);
            s12 = fmaf(gv.y, fv.z, s12); s13 = fmaf(gv.y, fv.w, s13);
            s20 = fmaf(gv.z, fv.x, s20); s21 = fmaf(gv.z, fv.y, s21);
            s22 = fmaf(gv.z, fv.z, s22); s23 = fmaf(gv.z, fv.w, s23);
            s30 = fmaf(gv.w, fv.x, s30); s31 = fmaf(gv.w, fv.y, s31);
            s32 = fmaf(gv.w, fv.z, s32); s33 = fmaf(gv.w, fv.w, s33);
        }

        float srow[4][4] = {{s00,s01,s02,s03},{s10,s11,s12,s13},
                            {s20,s21,s22,s23},{s30,s31,s32,s33}};

        // ---- Online softmax (reduce across the 16 tx threads of a row) -
#pragma unroll
        for (int i = 0; i < 4; i++) {
            float rmax = fmaxf(fmaxf(srow[i][0], srow[i][1]),
                               fmaxf(srow[i][2], srow[i][3]));
#pragma unroll
            for (int off = 8; off >= 1; off >>= 1)
                rmax = fmaxf(rmax, __shfl_xor_sync(0xffffffffu, rmax, off));

            float mnew  = fmaxf(m[i], rmax);
            float alpha = __expf(m[i] - mnew);

            float4 p;
            p.x = __expf(srow[i][0] - mnew);
            p.y = __expf(srow[i][1] - mnew);
            p.z = __expf(srow[i][2] - mnew);
            p.w = __expf(srow[i][3] - mnew);
            *(float4*)&sP[ty * 4 + i][tx * 4] = p;

            float psum = (p.x + p.y) + (p.z + p.w);
#pragma unroll
            for (int off = 8; off >= 1; off >>= 1)
                psum += __shfl_xor_sync(0xffffffffu, psum, off);

            l[i] = l[i] * alpha + psum;
            m[i] = mnew;
            acc[i][0] *= alpha;
            acc[i][1] *= alpha;
        }
        __syncthreads();

        // ---- GEMM2: acc[4][2] += P(rows) . HV(cols c0..c0+1) -----------
#pragma unroll 4
        for (int kk = 0; kk < BN; kk += 4) {
            float4 pv0 = *(const float4*)&sP[ty * 4 + 0][kk];
            float4 pv1 = *(const float4*)&sP[ty * 4 + 1][kk];
            float4 pv2 = *(const float4*)&sP[ty * 4 + 2][kk];
            float4 pv3 = *(const float4*)&sP[ty * 4 + 3][kk];
            float p0[4] = {pv0.x, pv0.y, pv0.z, pv0.w};
            float p1[4] = {pv1.x, pv1.y, pv1.z, pv1.w};
            float p2[4] = {pv2.x, pv2.y, pv2.z, pv2.w};
            float p3[4] = {pv3.x, pv3.y, pv3.z, pv3.w};
#pragma unroll
            for (int u = 0; u < 4; u++) {
                float2 h2 = *(const float2*)&sHV[kk + u][c0];
                acc[0][0] = fmaf(p0[u], h2.x, acc[0][0]);
                acc[0][1] = fmaf(p0[u], h2.y, acc[0][1]);
                acc[1][0] = fmaf(p1[u], h2.x, acc[1][0]);
                acc[1][1] = fmaf(p1[u], h2.y, acc[1][1]);
                acc[2][0] = fmaf(p2[u], h2.x, acc[2][0]);
                acc[2][1] = fmaf(p2[u], h2.y, acc[2][1]);
                acc[3][0] = fmaf(p3[u], h2.x, acc[3][0]);
                acc[3][1] = fmaf(p3[u], h2.y, acc[3][1]);
            }
        }
    }

    // ---- Epilogue: bhv = acc / l ---------------------------------------
#pragma unroll
    for (int i = 0; i < 4; i++) {
        float inv = 1.0f / l[i];
        size_t base = (size_t)(b * NTOK + q0 + ty * 4 + i) * CB + c0;
        g_bhv[base + 0] = acc[i][0] * inv;
        g_bhv[base + 1] = acc[i][1] * inv;
    }
}

// ---------------------------------------------------------------------------
// Kernel 3: out = x + gamma * (bhv @ Wo + bo)
// ---------------------------------------------------------------------------
__global__ __launch_bounds__(256) void out_kernel(
    const float* __restrict__ x,
    const float* __restrict__ Wo, const float* __restrict__ bo,
    const float* __restrict__ gamma,
    float* __restrict__ out)
{
    int idx = blockIdx.x * blockDim.x + threadIdx.x;  // [0, B*N*C)
    int row = idx >> 6;
    int c   = idx & 63;
    const float* br = g_bhv + (size_t)row * CB;
    float o = bo[c];
#pragma unroll 8
    for (int j = 0; j < CB; j++)
        o = fmaf(br[j], Wo[j * CIN + c], o);
    out[idx] = x[idx] + gamma[0] * o;
}

// ---------------------------------------------------------------------------
extern "C" void kernel_launch(void* const* d_in, const int* in_sizes, int n_in,
                              void* d_out, int out_size)
{
    const float* x     = (const float*)d_in[0];
    const float* Wf    = (const float*)d_in[1];
    const float* bf    = (const float*)d_in[2];
    const float* Wg    = (const float*)d_in[3];
    const float* bg    = (const float*)d_in[4];
    const float* Wh    = (const float*)d_in[5];
    const float* bh    = (const float*)d_in[6];
    const float* Wo    = (const float*)d_in[7];
    const float* bo    = (const float*)d_in[8];
    const float* gamma = (const float*)d_in[9];
    float* out = (float*)d_out;

    (void)in_sizes; (void)n_in; (void)out_size;

    proj_kernel<<<BATCH * NTOK * CB / 256, 256>>>(x, Wf, bf, Wg, bg, Wh, bh);

    dim3 agrid(NTOK / BM, BATCH);
    attn_kernel<<<agrid, NT>>>();

    out_kernel<<<BATCH * NTOK * CIN / 256, 256>>>(x, Wo, bo, gamma, out);
}

// round 3
// speedup vs baseline: 2.8483x; 2.8483x over previous
#include <cuda_runtime.h>
#include <cuda_bf16.h>

// ---------------------------------------------------------------------------
// Problem constants
// ---------------------------------------------------------------------------
#define NTOK 4096
#define CB   32
#define CIN  64
#define BATCH 2

#define QT     128                     // queries per block (8 warps x 16 rows)
#define KTILE  64                      // keys per tile
#define SPLITS 2
#define KTILES (NTOK / SPLITS / KTILE) // 32
#define KP     40                      // padded row stride (bf16 elems): conflict-free ldmatrix

// ---------------------------------------------------------------------------
// Scratch (no cudaMalloc allowed)
// ---------------------------------------------------------------------------
__device__ __align__(16) float g_f  [BATCH * NTOK * CB];
__device__ __align__(16) float g_g  [BATCH * NTOK * CB];
__device__ __align__(16) float g_hv [BATCH * NTOK * CB];
__device__ __align__(16) float g_bhv[BATCH * NTOK * CB];
__device__ __align__(16) float g_part[SPLITS][BATCH * NTOK * CB];
__device__ __align__(16) float g_m[SPLITS][BATCH * NTOK];
__device__ __align__(16) float g_l[SPLITS][BATCH * NTOK];

// ---------------------------------------------------------------------------
// Helpers
// ---------------------------------------------------------------------------
__device__ __forceinline__ unsigned smem_u32(const void* p) {
    unsigned a;
    asm("{ .reg .u64 t; cvta.to.shared.u64 t, %1; cvt.u32.u64 %0, t; }"
        : "=r"(a) : "l"(p));
    return a;
}

#define LDMX4(r, a) \
    asm volatile("ldmatrix.sync.aligned.m8n8.x4.shared.b16 {%0,%1,%2,%3}, [%4];" \
        : "=r"((r)[0]), "=r"((r)[1]), "=r"((r)[2]), "=r"((r)[3]) : "r"(a))
#define LDMX4T(r, a) \
    asm volatile("ldmatrix.sync.aligned.m8n8.x4.trans.shared.b16 {%0,%1,%2,%3}, [%4];" \
        : "=r"((r)[0]), "=r"((r)[1]), "=r"((r)[2]), "=r"((r)[3]) : "r"(a))

__device__ __forceinline__ void mma16816(float* d, const unsigned* a, const unsigned* b) {
    asm volatile(
        "mma.sync.aligned.m16n8k16.row.col.f32.bf16.bf16.f32 "
        "{%0,%1,%2,%3}, {%4,%5,%6,%7}, {%8,%9}, {%0,%1,%2,%3};"
        : "+f"(d[0]), "+f"(d[1]), "+f"(d[2]), "+f"(d[3])
        : "r"(a[0]), "r"(a[1]), "r"(a[2]), "r"(a[3]), "r"(b[0]), "r"(b[1]));
}

// fp32 -> (hi bf16, lo bf16 residual), pairs packed into bf16x2 words
__device__ __forceinline__ void cvt_pair(float f0, float f1, unsigned& hi, unsigned& lo) {
    __nv_bfloat162 h = __floats2bfloat162_rn(f0, f1);
    float r0 = f0 - __bfloat162float(h.x);
    float r1 = f1 - __bfloat162float(h.y);
    __nv_bfloat162 l = __floats2bfloat162_rn(r0, r1);
    hi = *(unsigned*)&h;
    lo = *(unsigned*)&l;
}

// Convert 8 consecutive floats to one uint4 of hi pairs and one of lo pairs
__device__ __forceinline__ void cvt8(const float4 a, const float4 b, uint4& hi, uint4& lo) {
    cvt_pair(a.x, a.y, hi.x, lo.x);
    cvt_pair(a.z, a.w, hi.y, lo.y);
    cvt_pair(b.x, b.y, hi.z, lo.z);
    cvt_pair(b.z, b.w, hi.w, lo.w);
}

// ---------------------------------------------------------------------------
// Kernel 1: projections. Each thread computes 4 output cols for one row,
// for all three projections. float4 W loads, float4 x loads.
// ---------------------------------------------------------------------------
__global__ __launch_bounds__(256) void proj_kernel(
    const float* __restrict__ x,
    const float* __restrict__ Wf, const float* __restrict__ bf,
    const float* __restrict__ Wg, const float* __restrict__ bg,
    const float* __restrict__ Wh, const float* __restrict__ bh)
{
    int idx = blockIdx.x * blockDim.x + threadIdx.x;   // [0, B*N*8)
    int row = idx >> 3;
    int c4  = (idx & 7) * 4;
    const float4* xr = (const float4*)(x + (size_t)row * CIN);
    float4 af = *(const float4*)(bf + c4);
    float4 ag = *(const float4*)(bg + c4);
    float4 ah = *(const float4*)(bh + c4);
#pragma unroll 4
    for (int k4 = 0; k4 < CIN / 4; k4++) {
        float4 xv = xr[k4];
        float xs[4] = {xv.x, xv.y, xv.z, xv.w};
#pragma unroll
        for (int j = 0; j < 4; j++) {
            int k = k4 * 4 + j;
            float4 wf = *(const float4*)(Wf + k * CB + c4);
            float4 wg = *(const float4*)(Wg + k * CB + c4);
            float4 wh = *(const float4*)(Wh + k * CB + c4);
            af.x = fmaf(xs[j], wf.x, af.x); af.y = fmaf(xs[j], wf.y, af.y);
            af.z = fmaf(xs[j], wf.z, af.z); af.w = fmaf(xs[j], wf.w, af.w);
            ag.x = fmaf(xs[j], wg.x, ag.x); ag.y = fmaf(xs[j], wg.y, ag.y);
            ag.z = fmaf(xs[j], wg.z, ag.z); ag.w = fmaf(xs[j], wg.w, ag.w);
            ah.x = fmaf(xs[j], wh.x, ah.x); ah.y = fmaf(xs[j], wh.y, ah.y);
            ah.z = fmaf(xs[j], wh.z, ah.z); ah.w = fmaf(xs[j], wh.w, ah.w);
        }
    }
    size_t o = (size_t)row * CB + c4;
    *(float4*)(g_f  + o) = af;
    *(float4*)(g_g  + o) = ag;
    *(float4*)(g_hv + o) = ah;
}

// ---------------------------------------------------------------------------
// Kernel 2: flash attention with mma.sync bf16 3-pass split (fp32-accurate)
// 256 threads = 8 warps; warp w owns query rows w*16..w*16+15.
// ---------------------------------------------------------------------------
__global__ __launch_bounds__(256, 1) void attn_kernel()
{
    __shared__ __nv_bfloat16 sQh[QT * KP],    sQl[QT * KP];
    __shared__ __nv_bfloat16 sKh[KTILE * KP], sKl[KTILE * KP];
    __shared__ __nv_bfloat16 sVh[KTILE * KP], sVl[KTILE * KP];

    const int b  = blockIdx.y;
    const int q0 = blockIdx.x * QT;
    const int k0 = blockIdx.z * (NTOK / SPLITS);
    const int t  = threadIdx.x;
    const int w  = t >> 5;
    const int lane = t & 31;

    // ---- Stage Q (once): thread handles half a row (16 floats) ----------
    {
        int row = t >> 1, half = t & 1;
        const float4* src = (const float4*)(g_g + (size_t)(b * NTOK + q0 + row) * CB + half * 16);
        float4 v0 = src[0], v1 = src[1], v2 = src[2], v3 = src[3];
        uint4 h0, l0, h1, l1;
        cvt8(v0, v1, h0, l0);
        cvt8(v2, v3, h1, l1);
        int e = row * KP + half * 16;
        *(uint4*)(sQh + e)     = h0;  *(uint4*)(sQh + e + 8) = h1;
        *(uint4*)(sQl + e)     = l0;  *(uint4*)(sQl + e + 8) = l1;
    }

    // ---- Prefetch + stage K/V tile 0 ------------------------------------
    const int krow = t >> 2, kq = t & 3;     // staging: row 0-63, col-quad 0-3
    {
        const float4* fs = (const float4*)(g_f  + (size_t)(b * NTOK + k0 + krow) * CB + kq * 8);
        const float4* hs = (const float4*)(g_hv + (size_t)(b * NTOK + k0 + krow) * CB + kq * 8);
        float4 ka = fs[0], kb = fs[1], va = hs[0], vb = hs[1];
        uint4 hi, lo;
        int e = krow * KP + kq * 8;
        cvt8(ka, kb, hi, lo);
        *(uint4*)(sKh + e) = hi;  *(uint4*)(sKl + e) = lo;
        cvt8(va, vb, hi, lo);
        *(uint4*)(sVh + e) = hi;  *(uint4*)(sVl + e) = lo;
    }
    __syncthreads();

    // ---- Load Q fragments (held in registers all kernel) -----------------
    unsigned qh[2][4], ql[2][4];
    {
        int arow = w * 16 + (lane & 15);
        int acol = (lane >> 4) * 8;
        LDMX4(qh[0], smem_u32(sQh + arow * KP + acol));
        LDMX4(qh[1], smem_u32(sQh + arow * KP + 16 + acol));
        LDMX4(ql[0], smem_u32(sQl + arow * KP + acol));
        LDMX4(ql[1], smem_u32(sQl + arow * KP + 16 + acol));
    }

    float m0 = -1e30f, m1 = -1e30f, l0 = 0.f, l1 = 0.f;
    float o[4][4];
#pragma unroll
    for (int nn = 0; nn < 4; nn++)
#pragma unroll
        for (int j = 0; j < 4; j++) o[nn][j] = 0.f;

    // ldmatrix addresses (constant per thread)
    const unsigned kaddr_h = smem_u32(sKh + ((lane & 7)) * KP + (lane >> 3) * 8);
    const unsigned kaddr_l = smem_u32(sKl + ((lane & 7)) * KP + (lane >> 3) * 8);
    const unsigned vbase_h = smem_u32(sVh + lane * KP);
    const unsigned vbase_l = smem_u32(sVl + lane * KP);

    for (int kt = 0; kt < KTILES; kt++) {
        // ---- Prefetch next tile into registers ---------------------------
        bool pf = (kt + 1 < KTILES);
        float4 ka, kb, va, vb;
        if (pf) {
            const float4* fs = (const float4*)(g_f  + (size_t)(b * NTOK + k0 + (kt + 1) * KTILE + krow) * CB + kq * 8);
            const float4* hs = (const float4*)(g_hv + (size_t)(b * NTOK + k0 + (kt + 1) * KTILE + krow) * CB + kq * 8);
            ka = fs[0]; kb = fs[1]; va = hs[0]; vb = hs[1];
        }

        // ---- GEMM1: S[16 x 64] = Q . K^T (3-pass bf16 split) -------------
        float s[8][4];
#pragma unroll
        for (int n = 0; n < 8; n++) {
            s[n][0] = s[n][1] = s[n][2] = s[n][3] = 0.f;
            unsigned kh[4], kl[4];
            LDMX4(kh, kaddr_h + n * 8 * KP * 2);   // byte offset: 8 rows * KP * 2B
            LDMX4(kl, kaddr_l + n * 8 * KP * 2);
            mma16816(s[n], qh[0], kh + 0);
            mma16816(s[n], qh[1], kh + 2);
            mma16816(s[n], ql[0], kh + 0);
            mma16816(s[n], ql[1], kh + 2);
            mma16816(s[n], qh[0], kl + 0);
            mma16816(s[n], qh[1], kl + 2);
        }

        // ---- Online softmax (rows fully inside warp; 4 lanes per row) ----
        float r0 = -1e30f, r1 = -1e30f;
#pragma unroll
        for (int n = 0; n < 8; n++) {
            r0 = fmaxf(r0, fmaxf(s[n][0], s[n][1]));
            r1 = fmaxf(r1, fmaxf(s[n][2], s[n][3]));
        }
        r0 = fmaxf(r0, __shfl_xor_sync(0xffffffffu, r0, 1));
        r0 = fmaxf(r0, __shfl_xor_sync(0xffffffffu, r0, 2));
        r1 = fmaxf(r1, __shfl_xor_sync(0xffffffffu, r1, 1));
        r1 = fmaxf(r1, __shfl_xor_sync(0xffffffffu, r1, 2));
        float mn0 = fmaxf(m0, r0), mn1 = fmaxf(m1, r1);
        float al0 = __expf(m0 - mn0), al1 = __expf(m1 - mn1);

        float ps0 = 0.f, ps1 = 0.f;
        unsigned ph[4][4], pl[4][4];            // [kstep][a-reg]
#pragma unroll
        for (int n = 0; n < 8; n++) {
            float p0 = __expf(s[n][0] - mn0);
            float p1 = __expf(s[n][1] - mn0);
            float p2 = __expf(s[n][2] - mn1);
            float p3 = __expf(s[n][3] - mn1);
            ps0 += p0 + p1;  ps1 += p2 + p3;
            int kk = n >> 1, hset = (n & 1) * 2;
            cvt_pair(p0, p1, ph[kk][hset + 0], pl[kk][hset + 0]);
            cvt_pair(p2, p3, ph[kk][hset + 1], pl[kk][hset + 1]);
        }
        ps0 += __shfl_xor_sync(0xffffffffu, ps0, 1);
        ps0 += __shfl_xor_sync(0xffffffffu, ps0, 2);
        ps1 += __shfl_xor_sync(0xffffffffu, ps1, 1);
        ps1 += __shfl_xor_sync(0xffffffffu, ps1, 2);
        l0 = l0 * al0 + ps0;  l1 = l1 * al1 + ps1;
        m0 = mn0;  m1 = mn1;

        // ---- Rescale O accumulators --------------------------------------
#pragma unroll
        for (int nn = 0; nn < 4; nn++) {
            o[nn][0] *= al0; o[nn][1] *= al0;
            o[nn][2] *= al1; o[nn][3] *= al1;
        }

        // ---- GEMM2: O += P . V (3-pass split; P from regs, V via ldmatrix.trans)
#pragma unroll
        for (int kkp = 0; kkp < 2; kkp++) {
            int kk0 = kkp * 2, kk1 = kkp * 2 + 1;
#pragma unroll
            for (int nn = 0; nn < 4; nn++) {
                unsigned vh[4], vl[4];
                unsigned off = (unsigned)(kkp * 32 * KP * 2 + nn * 8 * 2); // bytes
                LDMX4T(vh, vbase_h + off);
                LDMX4T(vl, vbase_l + off);
                mma16816(o[nn], ph[kk0], vh + 0);
                mma16816(o[nn], ph[kk1], vh + 2);
                mma16816(o[nn], pl[kk0], vh + 0);
                mma16816(o[nn], pl[kk1], vh + 2);
                mma16816(o[nn], ph[kk0], vl + 0);
                mma16816(o[nn], ph[kk1], vl + 2);
            }
        }

        // ---- Stage next tile ---------------------------------------------
        __syncthreads();
        if (pf) {
            uint4 hi, lo;
            int e = krow * KP + kq * 8;
            cvt8(ka, kb, hi, lo);
            *(uint4*)(sKh + e) = hi;  *(uint4*)(sKl + e) = lo;
            cvt8(va, vb, hi, lo);
            *(uint4*)(sVh + e) = hi;  *(uint4*)(sVl + e) = lo;
        }
        __syncthreads();
    }

    // ---- Epilogue: store unnormalized partial + m, l ---------------------
    {
        int z = blockIdx.z;
        int r = lane >> 2;
        int c = (lane & 3) * 2;
        int grow0 = b * NTOK + q0 + w * 16 + r;
        int grow1 = grow0 + 8;
        if ((lane & 3) == 0) {
            g_m[z][grow0] = m0;  g_l[z][grow0] = l0;
            g_m[z][grow1] = m1;  g_l[z][grow1] = l1;
        }
#pragma unroll
        for (int nn = 0; nn < 4; nn++) {
            *(float2*)&g_part[z][(size_t)grow0 * CB + nn * 8 + c] = make_float2(o[nn][0], o[nn][1]);
            *(float2*)&g_part[z][(size_t)grow1 * CB + nn * 8 + c] = make_float2(o[nn][2], o[nn][3]);
        }
    }
}

// ---------------------------------------------------------------------------
// Kernel 3: combine the 2 key-splits (flash merge), float4 vectorized
// ---------------------------------------------------------------------------
__global__ __launch_bounds__(256) void combine_kernel()
{
    int idx = blockIdx.x * blockDim.x + threadIdx.x;   // [0, B*N*8)
    int rowid = idx >> 3;
    float m0 = g_m[0][rowid], m1 = g_m[1][rowid];
    float l0 = g_l[0][rowid], l1 = g_l[1][rowid];
    float M  = fmaxf(m0, m1);
    float w0 = __expf(m0 - M), w1 = __expf(m1 - M);
    float inv = 1.0f / (l0 * w0 + l1 * w1);
    float4 p0 = *(const float4*)(&g_part[0][0] + (size_t)idx * 4);
    float4 p1 = *(const float4*)(&g_part[1][0] + (size_t)idx * 4);
    float4 r;
    r.x = (p0.x * w0 + p1.x * w1) * inv;
    r.y = (p0.y * w0 + p1.y * w1) * inv;
    r.z = (p0.z * w0 + p1.z * w1) * inv;
    r.w = (p0.w * w0 + p1.w * w1) * inv;
    *(float4*)(g_bhv + (size_t)idx * 4) = r;
}

// ---------------------------------------------------------------------------
// Kernel 4: out = x + gamma * (bhv @ Wo + bo), float4 vectorized
// ---------------------------------------------------------------------------
__global__ __launch_bounds__(256) void out_kernel(
    const float* __restrict__ x,
    const float* __restrict__ Wo, const float* __restrict__ bo,
    const float* __restrict__ gamma,
    float* __restrict__ out)
{
    int idx = blockIdx.x * blockDim.x + threadIdx.x;   // [0, B*N*16)
    int row = idx >> 4;
    int c4  = (idx & 15) * 4;
    const float4* br = (const float4*)(g_bhv + (size_t)row * CB);
    float4 o = *(const float4*)(bo + c4);
#pragma unroll 2
    for (int j4 = 0; j4 < CB / 4; j4++) {
        float4 bv = br[j4];
        float bs[4] = {bv.x, bv.y, bv.z, bv.w};
#pragma unroll
        for (int j = 0; j < 4; j++) {
            float4 wv = *(const float4*)(Wo + (j4 * 4 + j) * CIN + c4);
            o.x = fmaf(bs[j], wv.x, o.x);
            o.y = fmaf(bs[j], wv.y, o.y);
            o.z = fmaf(bs[j], wv.z, o.z);
            o.w = fmaf(bs[j], wv.w, o.w);
        }
    }
    float gm = gamma[0];
    float4 xv = *(const float4*)(x + (size_t)row * CIN + c4);
    float4 r;
    r.x = xv.x + gm * o.x;  r.y = xv.y + gm * o.y;
    r.z = xv.z + gm * o.z;  r.w = xv.w + gm * o.w;
    *(float4*)(out + (size_t)row * CIN + c4) = r;
}

// ---------------------------------------------------------------------------
extern "C" void kernel_launch(void* const* d_in, const int* in_sizes, int n_in,
                              void* d_out, int out_size)
{
    const float* x     = (const float*)d_in[0];
    const float* Wf    = (const float*)d_in[1];
    const float* bf    = (const float*)d_in[2];
    const float* Wg    = (const float*)d_in[3];
    const float* bg    = (const float*)d_in[4];
    const float* Wh    = (const float*)d_in[5];
    const float* bh    = (const float*)d_in[6];
    const float* Wo    = (const float*)d_in[7];
    const float* bo    = (const float*)d_in[8];
    const float* gamma = (const float*)d_in[9];
    float* out = (float*)d_out;
    (void)in_sizes; (void)n_in; (void)out_size;

    proj_kernel<<<BATCH * NTOK * 8 / 256, 256>>>(x, Wf, bf, Wg, bg, Wh, bh);

    dim3 agrid(NTOK / QT, BATCH, SPLITS);
    attn_kernel<<<agrid, 256>>>();

    combine_kernel<<<BATCH * NTOK * 8 / 256, 256>>>();

    out_kernel<<<BATCH * NTOK * 16 / 256, 256>>>(x, Wo, bo, gamma, out);
}